// round 2
// baseline (speedup 1.0000x reference)
#include <cuda_runtime.h>

// SIRD batched RK4 integrator, sm_103a.
// T=2048 scenarios, one thread per scenario (64 blocks x 32 threads).
// Latency-bound on the serial RK4 chain; algebra restructured so the
// per-substep critical path is ~3-4 FMA levels per RK4 stage.
//
// State per thread: I, D, and bS = (beta/N)*S (S never needed directly).
// Exact-equivalent algebra to the reference:
//   new_inf f = b*S*I = bS*I
//   kS = -f            -> bS' updates via fmaf(-h*b, f, bS)
//   kI = f - (g+mu)*I  -> folded FMAs
//   kD = mu*I          -> D += h6*mu*(I1 + 2*I2 + 2*I3 + I4)

#define T_PTS 2048
#define N_POP 1.0e7f

__global__ void __launch_bounds__(32, 1)
sird_kernel(const float* __restrict__ alpha, float2* __restrict__ out) {
    const int s = blockIdx.x * 32 + threadIdx.x;

    const float beta  = alpha[s * 3 + 0];
    const float gamma = alpha[s * 3 + 1];
    const float mu    = alpha[s * 3 + 2];

    const float invN = 1.0f / N_POP;
    const float b    = beta * invN;      // beta/N
    const float g    = gamma + mu;       // total removal rate

    const float dt  = 0.125f;            // 1/SUBSTEPS, exact
    const float h2  = 0.0625f;           // dt/2, exact
    const float h6  = dt / 6.0f;

    // Precomputed per-thread constants (hoisted off the chain)
    const float c2    = fmaf(-h2, g, 1.0f);  // 1 - h2*g
    const float h2g   = h2 * g;
    const float dtg   = dt * g;
    const float h2b   = h2 * b;
    const float dtb   = dt * b;
    const float h6b   = h6 * b;
    const float h6g   = h6 * g;
    const float h6mu  = h6 * mu;

    float I  = 1.0f;
    float D  = 0.0f;
    float bS = b * (N_POP - 1.0f);       // b * S0

    float2* __restrict__ orow = out + (size_t)s * T_PTS;
    orow[0] = make_float2(1.0f, 0.0f);   // t = 0: (I0, D0)

    for (int t = 1; t < T_PTS; ++t) {
        #pragma unroll
        for (int k = 0; k < 8; ++k) {
            // ---- stage 1 ----
            float f1  = bS * I;                              // new_inf_1
            float I2  = fmaf(h2, f1, c2 * I);                // I + h2*(f1 - g*I)
            float bS2 = fmaf(-h2b, f1, bS);
            // ---- stage 2 ----
            float f2  = bS2 * I2;
            float I3  = fmaf(h2, f2, fmaf(-h2g, I2, I));     // I + h2*(f2 - g*I2)
            float bS3 = fmaf(-h2b, f2, bS);
            // ---- stage 3 ----
            float f3  = bS3 * I3;
            float I4  = fmaf(dt, f3, fmaf(-dtg, I3, I));     // I + dt*(f3 - g*I3)
            float bS4 = fmaf(-dtb, f3, bS);
            // ---- stage 4 ----
            float f4  = bS4 * I4;

            // Weighted sums (computed as stages finish; only last adds on path)
            float pf   = fmaf(2.0f, f3, fmaf(2.0f, f2, f1)); // f1 + 2f2 + 2f3
            float sumf = pf + f4;                            // Σw f
            float pI   = fmaf(2.0f, I3, fmaf(2.0f, I2, I));  // I1 + 2I2 + 2I3
            float wI   = pI + I4;                            // Σw I_stage

            // I_next = I + h6*(Σw f - g*Σw I)
            float baseI = fmaf(h6, pf, I);                   // ready before f4
            I  = fmaf(h6, f4, fmaf(-h6g, wI, baseI));
            // D_next = D + h6*mu*Σw I   (exactly reference kD combine)
            D  = fmaf(h6mu, wI, D);
            // bS_next = bS - h6*b*Σw f   (== b*(S - h6*Σw f))
            bS = fmaf(-h6b, sumf, bS);
        }
        orow[t] = make_float2(I, D);
    }
}

extern "C" void kernel_launch(void* const* d_in, const int* in_sizes, int n_in,
                              void* d_out, int out_size) {
    const float* alpha = (const float*)d_in[0];
    float2* out = (float2*)d_out;
    sird_kernel<<<T_PTS / 32, 32>>>(alpha, out);
}

// round 5
// speedup vs baseline: 1.8727x; 1.8727x over previous
#include <cuda_runtime.h>

// SIRD batched RK4 integrator, sm_103a — round 3.
// T=2048 scenarios, one thread per scenario (64 blocks x 32 threads).
//
// Round-2 ncu showed issue=50%: per-warp FFMA issue floor (rt_SMSP=2), tied
// with the dependency chain. Two changes:
//  1) b-scaled state (bI, bS) = (b*I, b*S): all S-side and f-weighted FMA
//     multipliers become compile-time IMMEDIATES -> FFMA-imm rt=1 (2x issue).
//     Scale-invariant dynamics, exact up to rounding; unscale at output.
//  2) SUBSTEPS 8 -> 4 (dt = 0.25): RK4 step-doubling error ~3e-5 relative,
//     well under the 1e-3 gate; halves the serial chain.
//
// Scaled dynamics (f' = b*f = bS*bI):
//   bI' updates: bI_{k+1} = h*f' + (bI - h*g*bI_k)      (g multipliers: reg)
//   bS' updates: bS_{k+1} = bS - h*f'                    (IMMEDIATE h)
//   D += h6*(mu/b) * (bI1 + 2 bI2 + 2 bI3 + bI4)

#define T_PTS 2048
#define SUB   4

__global__ void __launch_bounds__(32, 1)
sird_kernel(const float* __restrict__ alpha, float2* __restrict__ out) {
    const int s = blockIdx.x * 32 + threadIdx.x;

    const float beta  = alpha[s * 3 + 0];
    const float gamma = alpha[s * 3 + 1];
    const float mu    = alpha[s * 3 + 2];

    float b = beta * 1.0e-7f;            // beta / N
    b = fmaxf(b, 1.0e-20f);              // beta==0 guard (scale-invariant)
    const float g = gamma + mu;

    // Compile-time immediates (become FFMA-imm, rt=1)
    constexpr float dtc = 1.0f / SUB;        // 0.25
    constexpr float h2c = dtc * 0.5f;        // 0.125
    constexpr float h6c = dtc / 6.0f;

    // Runtime per-thread constants (reg-form FFMA, rt=2)
    const float h2g    = h2c * g;
    const float dtg    = dtc * g;
    const float h6g    = h6c * g;
    const float c2     = 1.0f - h2g;
    const float inv_b  = 1.0f / b;
    const float h6mu_b = h6c * mu * inv_b;

    float bI = b;                        // b * I0   (I0 = 1)
    float bS = b * (1.0e7f - 1.0f);      // b * S0
    float D  = 0.0f;

    float2* __restrict__ orow = out + (size_t)s * T_PTS;
    orow[0] = make_float2(1.0f, 0.0f);

#define SUBSTEP() do {                                           \
        float f1  = bS * bI;                                     \
        float cbI = c2 * bI;                                     \
        float bI2 = fmaf( h2c, f1, cbI);                         \
        float bS2 = fmaf(-h2c, f1, bS);                          \
        float f2  = bS2 * bI2;                                   \
        float in3 = fmaf(-h2g, bI2, bI);                         \
        float bI3 = fmaf( h2c, f2, in3);                         \
        float bS3 = fmaf(-h2c, f2, bS);                          \
        float f3  = bS3 * bI3;                                   \
        float in4 = fmaf(-dtg, bI3, bI);                         \
        float bI4 = fmaf( dtc, f3, in4);                         \
        float bS4 = fmaf(-dtc, f3, bS);                          \
        float f4  = bS4 * bI4;                                   \
        float pf  = fmaf(2.0f, f3, fmaf(2.0f, f2, f1));          \
        float sumf = pf + f4;                                    \
        float pI  = fmaf(2.0f, bI3, fmaf(2.0f, bI2, bI));        \
        float wI  = pI + bI4;                                    \
        float baseI = fmaf(h6c, pf, bI);                         \
        bI = fmaf(h6c, f4, fmaf(-h6g, wI, baseI));               \
        D  = fmaf(h6mu_b, wI, D);                                \
        bS = fmaf(-h6c, sumf, bS);                               \
    } while (0)

    // t = 1 (odd leading point), then pairs of unit steps with STG.128
    #pragma unroll
    for (int k = 0; k < SUB; ++k) SUBSTEP();
    orow[1] = make_float2(bI * inv_b, D);

    for (int t = 2; t < T_PTS; t += 2) {
        #pragma unroll
        for (int k = 0; k < SUB; ++k) SUBSTEP();
        float Ia = bI * inv_b;
        float Da = D;
        #pragma unroll
        for (int k = 0; k < SUB; ++k) SUBSTEP();
        float4 pkt = make_float4(Ia, Da, bI * inv_b, D);
        *reinterpret_cast<float4*>(orow + t) = pkt;   // 16B-aligned: t even
    }
#undef SUBSTEP
}

extern "C" void kernel_launch(void* const* d_in, const int* in_sizes, int n_in,
                              void* d_out, int out_size) {
    const float* alpha = (const float*)d_in[0];
    float2* out = (float2*)d_out;
    sird_kernel<<<T_PTS / 32, 32>>>(alpha, out);
}

// round 6
// speedup vs baseline: 3.8862x; 2.0751x over previous
#include <cuda_runtime.h>

// SIRD batched RK4 integrator, sm_103a — round 6.
// T=2048 scenarios, one thread per scenario (64 blocks x 32 threads).
// Serial-chain latency bound: ~36-cycle RK4 dependency chain per substep.
//
// Round-5 data: SUB=4 gave rel_err 8.4e-6 vs a 1e-3 gate -> >100x headroom.
// RK4 truncation ~dt^4, so SUB=2 (dt=0.5) lands ~1.3e-4: still 7x margin,
// and halves the serial chain. Also unroll 4 time points per iteration
// (1 branch / 4t, two STG.128) and pointer-increment addressing to cut the
// ~13 cyc/substep loop+store overhead observed in round 5.
//
// b-scaled state (bI, bS) = (b*I, b*S): immediate-form FFMA (rt=1) for all
// h-multipliers; scale-invariant, unscaled only at the 2048 output points.

#define T_PTS 2048
#define SUB   2

__global__ void __launch_bounds__(32, 1)
sird_kernel(const float* __restrict__ alpha, float2* __restrict__ out) {
    const int s = blockIdx.x * 32 + threadIdx.x;

    const float beta  = alpha[s * 3 + 0];
    const float gamma = alpha[s * 3 + 1];
    const float mu    = alpha[s * 3 + 2];

    float b = beta * 1.0e-7f;            // beta / N
    b = fmaxf(b, 1.0e-20f);              // beta==0 guard (scale-invariant)
    const float g = gamma + mu;

    // Compile-time immediates (FFMA-imm, rt=1)
    constexpr float dtc = 1.0f / SUB;        // 0.5
    constexpr float h2c = dtc * 0.5f;        // 0.25
    constexpr float h6c = dtc / 6.0f;

    // Runtime per-thread constants (reg-form FFMA, rt=2)
    const float h2g    = h2c * g;
    const float dtg    = dtc * g;
    const float h6g    = h6c * g;
    const float c2     = 1.0f - h2g;
    const float inv_b  = 1.0f / b;
    const float h6mu_b = h6c * mu * inv_b;

    float bI = b;                        // b * I0   (I0 = 1)
    float bS = b * (1.0e7f - 1.0f);      // b * S0
    float D  = 0.0f;

    float2* __restrict__ op = out + (size_t)s * T_PTS;
    op[0] = make_float2(1.0f, 0.0f);

#define SUBSTEP() do {                                           \
        float f1  = bS * bI;                                     \
        float cbI = c2 * bI;                                     \
        float bI2 = fmaf( h2c, f1, cbI);                         \
        float bS2 = fmaf(-h2c, f1, bS);                          \
        float f2  = bS2 * bI2;                                   \
        float in3 = fmaf(-h2g, bI2, bI);                         \
        float bI3 = fmaf( h2c, f2, in3);                         \
        float bS3 = fmaf(-h2c, f2, bS);                          \
        float f3  = bS3 * bI3;                                   \
        float in4 = fmaf(-dtg, bI3, bI);                         \
        float bI4 = fmaf( dtc, f3, in4);                         \
        float bS4 = fmaf(-dtc, f3, bS);                          \
        float f4  = bS4 * bI4;                                   \
        float pf  = fmaf(2.0f, f3, fmaf(2.0f, f2, f1));          \
        float sumf = pf + f4;                                    \
        float pI  = fmaf(2.0f, bI3, fmaf(2.0f, bI2, bI));        \
        float wI  = pI + bI4;                                    \
        float baseI = fmaf(h6c, pf, bI);                         \
        bI = fmaf(h6c, f4, fmaf(-h6g, wI, baseI));               \
        D  = fmaf(h6mu_b, wI, D);                                \
        bS = fmaf(-h6c, sumf, bS);                               \
    } while (0)

#define UNITSTEP() do { SUBSTEP(); SUBSTEP(); } while (0)

    // t = 1..3 (odd leading points), then blocks of 4 with two STG.128
    UNITSTEP();
    op[1] = make_float2(bI * inv_b, D);
    UNITSTEP();
    float Ix = bI * inv_b, Dx = D;
    UNITSTEP();
    *reinterpret_cast<float4*>(op + 2) = make_float4(Ix, Dx, bI * inv_b, D);

    float4* __restrict__ p4 = reinterpret_cast<float4*>(op + 4);
    const float4* __restrict__ p4end = reinterpret_cast<float4*>(op + T_PTS);

    while (p4 != p4end) {
        UNITSTEP();
        float Ia = bI * inv_b, Da = D;
        UNITSTEP();
        p4[0] = make_float4(Ia, Da, bI * inv_b, D);
        UNITSTEP();
        float Ic = bI * inv_b, Dc = D;
        UNITSTEP();
        p4[1] = make_float4(Ic, Dc, bI * inv_b, D);
        p4 += 2;
    }
#undef UNITSTEP
#undef SUBSTEP
}

extern "C" void kernel_launch(void* const* d_in, const int* in_sizes, int n_in,
                              void* d_out, int out_size) {
    const float* alpha = (const float*)d_in[0];
    float2* out = (float2*)d_out;
    sird_kernel<<<T_PTS / 32, 32>>>(alpha, out);
}

// round 8
// speedup vs baseline: 7.2106x; 1.8554x over previous
#include <cuda_runtime.h>

// SIRD batched RK4 integrator, sm_103a — round 7.
// T=2048 scenarios, one thread per scenario (64 blocks x 32 threads).
//
// Round-6 data: rel_err scaled only x1.4 per dt-doubling (norm dominated by
// plateau values where RK4 error cancels) -> 85x budget left. So:
//  1) SUB 2 -> 1 (dt = 1.0). Stability fine (lambda*dt = 0.5 << 2.78).
//  2) Chain surgery 36 -> 32 cycles/substep:
//     - bS: bS - h6(pf + f4) computed as fmaf(-h6c, f4, bS_pre), with
//       bS_pre = fmaf(-h6c, pf, bS) precomputed -> 1 level post-f4.
//     - bI: h6*f4 - h6g*bI4 == bI4*(h6*bS4 - h6g); u = fmaf(h6c,bS4,-h6g)
//       is ready before f4, so bI = fmaf(bI4, u, P) -> f4 leaves the bI
//       critical path. 8 FMA levels = 32 cycles per substep.
//  3) 8 time points per loop iteration, 4x STG.128.
//
// b-scaled state (bI, bS) = (b*I, b*S): immediate-form FFMA for h-constants.

#define T_PTS 2048

__global__ void __launch_bounds__(32, 1)
sird_kernel(const float* __restrict__ alpha, float2* __restrict__ out) {
    const int s = blockIdx.x * 32 + threadIdx.x;

    const float beta  = alpha[s * 3 + 0];
    const float gamma = alpha[s * 3 + 1];
    const float mu    = alpha[s * 3 + 2];

    float b = beta * 1.0e-7f;            // beta / N
    b = fmaxf(b, 1.0e-20f);              // beta==0 guard (scale-invariant)
    const float g = gamma + mu;

    // Compile-time immediates (FFMA-imm, rt=1)
    constexpr float dtc = 1.0f;          // SUB = 1
    constexpr float h2c = 0.5f;
    constexpr float h6c = 1.0f / 6.0f;

    // Runtime per-thread constants (reg-form FFMA, rt=2)
    const float h2g    = h2c * g;
    const float dtg    = dtc * g;
    const float mh6g   = -(h6c * g);
    const float c2     = 1.0f - h2g;
    const float inv_b  = 1.0f / b;
    const float h6mu_b = h6c * mu * inv_b;

    float bI = b;                        // b * I0   (I0 = 1)
    float bS = b * (1.0e7f - 1.0f);      // b * S0
    float D  = 0.0f;

    float2* __restrict__ op = out + (size_t)s * T_PTS;
    op[0] = make_float2(1.0f, 0.0f);

#define SUBSTEP() do {                                            \
        float f1   = bS * bI;                                     \
        float cbI  = c2 * bI;                                     \
        float bI2  = fmaf( h2c, f1, cbI);                         \
        float bS2  = fmaf(-h2c, f1, bS);                          \
        float f2   = bS2 * bI2;                                   \
        float preI = fmaf(2.0f, bI2, bI);                         \
        float in3  = fmaf(-h2g, bI2, bI);                         \
        float bI3  = fmaf( h2c, f2, in3);                         \
        float bS3  = fmaf(-h2c, f2, bS);                          \
        float pref = fmaf(2.0f, f2, f1);                          \
        float f3   = bS3 * bI3;                                   \
        float pI   = fmaf(2.0f, bI3, preI);                       \
        float in4  = fmaf(-dtg, bI3, bI);                         \
        float bI4  = fmaf( dtc, f3, in4);                         \
        float bS4  = fmaf(-dtc, f3, bS);                          \
        float pf   = fmaf(2.0f, f3, pref);                        \
        float P    = fmaf(h6c, pf, fmaf(mh6g, pI, bI));           \
        float bSp  = fmaf(-h6c, pf, bS);                          \
        float f4   = bS4 * bI4;                                   \
        float u    = fmaf(h6c, bS4, mh6g);                        \
        float wI   = pI + bI4;                                    \
        bI = fmaf(bI4, u, P);                                     \
        bS = fmaf(-h6c, f4, bSp);                                 \
        D  = fmaf(h6mu_b, wI, D);                                 \
    } while (0)

    // Prologue: t = 1 (float2), t = 2..7 (three STG.128)
    SUBSTEP();
    op[1] = make_float2(bI * inv_b, D);
    {
        SUBSTEP();
        float Ia = bI * inv_b, Da = D;
        SUBSTEP();
        *reinterpret_cast<float4*>(op + 2) = make_float4(Ia, Da, bI * inv_b, D);
        SUBSTEP();
        float Ic = bI * inv_b, Dc = D;
        SUBSTEP();
        *reinterpret_cast<float4*>(op + 4) = make_float4(Ic, Dc, bI * inv_b, D);
        SUBSTEP();
        float Ie = bI * inv_b, De = D;
        SUBSTEP();
        *reinterpret_cast<float4*>(op + 6) = make_float4(Ie, De, bI * inv_b, D);
    }

    // Main loop: 8 time points per iteration, 4x STG.128
    float4* __restrict__ p4 = reinterpret_cast<float4*>(op + 8);
    const float4* __restrict__ p4end = reinterpret_cast<float4*>(op + T_PTS);

    while (p4 != p4end) {
        #pragma unroll
        for (int j = 0; j < 4; ++j) {
            SUBSTEP();
            float Ia = bI * inv_b, Da = D;
            SUBSTEP();
            p4[j] = make_float4(Ia, Da, bI * inv_b, D);
        }
        p4 += 4;
    }
#undef SUBSTEP
}

extern "C" void kernel_launch(void* const* d_in, const int* in_sizes, int n_in,
                              void* d_out, int out_size) {
    const float* alpha = (const float*)d_in[0];
    float2* out = (float2*)d_out;
    sird_kernel<<<T_PTS / 32, 32>>>(alpha, out);
}

// round 11
// speedup vs baseline: 8.5207x; 1.1817x over previous
#include <cuda_runtime.h>

// SIRD batched integrator, sm_103a — round 10: Kutta RK3, dt=1 (re-bench;
// round 9 was an infra failure, theory untested).
// T=2048 scenarios, one thread per scenario (64 blocks x 32 threads).
//
// Round-8 audit: RK4 substep = 38 weighted issue cycles vs 32-cycle chain ->
// ISSUE-bound. Error budget 33x (rel_err 3e-5, norm plateau-dominated).
// 3rd-order Kutta RK3 (3 stages): ~31 issue cycles, 24-cycle chain.
// Calibrated error prediction ~3-6e-4 < 1e-3 gate.
//
// Scaled state (x, y) = (b*I, b*S), b = beta/N; f = y*x.
//   kx = f - g*x, ky = -f, kD = (mu/b)*x
// Kutta RK3: q2 = q + dt/2*k1; q3 = q - dt*k1 + 2dt*k2;
//            q' = q + dt/6*(k1 + 4k2 + k3),  dt = 1.
// x-combine uses v = h6*y3 - h6*g so x' = x3*v + base closes one FMA level
// after stage 3 (f3 never enters the x critical path; it only feeds y').

#define T_PTS 2048

__global__ void __launch_bounds__(32, 1)
sird_kernel(const float* __restrict__ alpha, float2* __restrict__ out) {
    const int s = blockIdx.x * 32 + threadIdx.x;

    const float beta  = alpha[s * 3 + 0];
    const float gamma = alpha[s * 3 + 1];
    const float mu    = alpha[s * 3 + 2];

    float b = beta * 1.0e-7f;            // beta / N
    b = fmaxf(b, 1.0e-20f);              // beta==0 guard (scale-invariant)
    const float g = gamma + mu;

    constexpr float h6c = 1.0f / 6.0f;   // dt/6, dt = 1

    // Runtime per-thread constants
    const float cA     = fmaf(-0.5f, g, 1.0f);   // 1 - g/2
    const float cB     = g + 1.0f;               // 1 + g
    const float mg2    = -2.0f * g;
    const float mh6g   = -(h6c * g);
    const float inv_b  = 1.0f / b;
    const float h6mu_b = h6c * mu * inv_b;

    float x = b;                         // b * I0   (I0 = 1)
    float y = b * (1.0e7f - 1.0f);       // b * S0
    float D = 0.0f;

    float2* __restrict__ op = out + (size_t)s * T_PTS;
    op[0] = make_float2(1.0f, 0.0f);

#define SUBSTEP() do {                                            \
        float f1   = y * x;                                       \
        float cAx  = cA * x;                                      \
        float cBx  = cB * x;                                      \
        float x2   = fmaf( 0.5f, f1, cAx);                        \
        float y2   = fmaf(-0.5f, f1, y);                          \
        float p3a  = cBx - f1;                                    \
        float p3c  = y + f1;                                      \
        float f2   = y2 * x2;                                     \
        float p3b  = fmaf(mg2, x2, p3a);                          \
        float pxw  = fmaf(4.0f, x2, x);                           \
        float x3   = fmaf( 2.0f, f2, p3b);                        \
        float y3   = fmaf(-2.0f, f2, p3c);                        \
        float pf   = fmaf(4.0f, f2, f1);                          \
        float W    = fmaf(mh6g, pxw, x);                          \
        float base = fmaf(h6c, pf, W);                            \
        float C    = fmaf(-h6c, pf, y);                           \
        float v    = fmaf(h6c, y3, mh6g);                         \
        float f3   = y3 * x3;                                     \
        float pD   = x3 + pxw;                                    \
        x = fmaf(x3, v, base);                                    \
        y = fmaf(-h6c, f3, C);                                    \
        D = fmaf(h6mu_b, pD, D);                                  \
    } while (0)

    // Prologue: t = 1 (float2), t = 2..7 (three STG.128)
    SUBSTEP();
    op[1] = make_float2(x * inv_b, D);
    {
        SUBSTEP();
        float Ia = x * inv_b, Da = D;
        SUBSTEP();
        *reinterpret_cast<float4*>(op + 2) = make_float4(Ia, Da, x * inv_b, D);
        SUBSTEP();
        float Ic = x * inv_b, Dc = D;
        SUBSTEP();
        *reinterpret_cast<float4*>(op + 4) = make_float4(Ic, Dc, x * inv_b, D);
        SUBSTEP();
        float Ie = x * inv_b, De = D;
        SUBSTEP();
        *reinterpret_cast<float4*>(op + 6) = make_float4(Ie, De, x * inv_b, D);
    }

    // Main loop: 8 time points per iteration, 4x STG.128
    float4* __restrict__ p4 = reinterpret_cast<float4*>(op + 8);
    const float4* __restrict__ p4end = reinterpret_cast<float4*>(op + T_PTS);

    while (p4 != p4end) {
        #pragma unroll
        for (int j = 0; j < 4; ++j) {
            SUBSTEP();
            float Ia = x * inv_b, Da = D;
            SUBSTEP();
            p4[j] = make_float4(Ia, Da, x * inv_b, D);
        }
        p4 += 4;
    }
#undef SUBSTEP
}

extern "C" void kernel_launch(void* const* d_in, const int* in_sizes, int n_in,
                              void* d_out, int out_size) {
    const float* alpha = (const float*)d_in[0];
    float2* out = (float2*)d_out;
    sird_kernel<<<T_PTS / 32, 32>>>(alpha, out);
}

// round 13
// speedup vs baseline: 8.8320x; 1.0365x over previous
#include <cuda_runtime.h>

// SIRD batched integrator, sm_103a — round 12: Kutta RK3 dt=1 +
// warp-specialized producer/consumer.
// 64 blocks x 64 threads: warp 0 integrates 32 scenarios (1/lane),
// warp 1 (same-lane scenario) does unscale + D-reconstruction + STG.
//
// Key move: RK methods preserve linear invariants exactly, so
//   D = (mu/g) * (N - S - I)
// can be reconstructed by the consumer from (x, y) = (b*I, b*S).
// Producer drops D/pD from the loop (-3 weighted cyc/substep) and replaces
// unscale(2)+STG(6) per point with one STS.128 per 2 points (~2 cyc).
// Ping-pong smem double buffer, one __syncthreads per 32-point batch.
//
// Producer substep: 20 FMA-pipe ops (12 imm-form rt=1, 8 reg-form rt=2)
// ~28 weighted issue cycles, 24-cycle dependency chain.

#define T_PTS 2048
#define BATCH 32                   // points per batch
#define NB    (T_PTS / BATCH)      // 64 batches

__global__ void __launch_bounds__(64, 1)
sird_kernel(const float* __restrict__ alpha, float2* __restrict__ out) {
    __shared__ float4 buf[2][BATCH / 2][32];   // [slot][pair][lane] = x0,y0,x1,y1

    const int lane = threadIdx.x & 31;
    const int wid  = threadIdx.x >> 5;
    const int scen = blockIdx.x * 32 + lane;

    const float beta  = alpha[scen * 3 + 0];
    const float gamma = alpha[scen * 3 + 1];
    const float mu    = alpha[scen * 3 + 2];

    float b = fmaxf(beta * 1.0e-7f, 1.0e-20f);   // beta/N, scale-invariant guard
    const float g = gamma + mu;

    constexpr float h6c = 1.0f / 6.0f;

    // ---- producer state/constants (warp 0) ----
    const float cA   = fmaf(-0.5f, g, 1.0f);
    const float cB   = g + 1.0f;
    const float mg2  = -2.0f * g;
    const float mh6g = -(h6c * g);
    float x = b;                        // b * I0
    float y = b * (1.0e7f - 1.0f);      // b * S0

    // ---- consumer constants (warp 1) ----
    const float inv_b = 1.0f / b;
    const float gs    = fmaxf(g, 1.0e-30f);
    const float cD    = (mu / gs) * inv_b;     // mu=0 -> cD=0 -> D == 0 exact
    const float bN    = b * 1.0e7f;
    float2* __restrict__ op = out + (size_t)scen * T_PTS;

#define SUBSTEP() do {                                            \
        float f1   = y * x;                                       \
        float cAx  = cA * x;                                      \
        float cBx  = cB * x;                                      \
        float x2   = fmaf( 0.5f, f1, cAx);                        \
        float y2   = fmaf(-0.5f, f1, y);                          \
        float p3a  = cBx - f1;                                    \
        float p3c  = y + f1;                                      \
        float f2   = y2 * x2;                                     \
        float p3b  = fmaf(mg2, x2, p3a);                          \
        float pxw  = fmaf(4.0f, x2, x);                           \
        float x3   = fmaf( 2.0f, f2, p3b);                        \
        float y3   = fmaf(-2.0f, f2, p3c);                        \
        float pf   = fmaf(4.0f, f2, f1);                          \
        float W    = fmaf(mh6g, pxw, x);                          \
        float base = fmaf(h6c, pf, W);                            \
        float C    = fmaf(-h6c, pf, y);                           \
        float v    = fmaf(h6c, y3, mh6g);                         \
        float f3   = y3 * x3;                                     \
        x = fmaf(x3, v, base);                                    \
        y = fmaf(-h6c, f3, C);                                    \
    } while (0)

    for (int k = 0; k <= NB; ++k) {
        if (wid == 0) {
            if (k < NB) {
                // produce points t = k*BATCH .. k*BATCH+31 into slot k&1
                float4* bp = &buf[k & 1][0][lane];
                #pragma unroll
                for (int p = 0; p < BATCH / 2; ++p) {
                    float x0 = x, y0 = y;      // point t = k*BATCH + 2p
                    SUBSTEP();                 // -> odd point
                    bp[p * 32] = make_float4(x0, y0, x, y);
                    SUBSTEP();                 // -> next even point
                }
                // (final iteration computes one point past t=2047; benign)
            }
        } else if (k > 0) {
            // drain batch k-1 from slot (k-1)&1
            const float4* bp = &buf[(k - 1) & 1][0][lane];
            float4* o4 = reinterpret_cast<float4*>(op + (k - 1) * BATCH);
            #pragma unroll
            for (int p = 0; p < BATCH / 2; ++p) {
                float4 s = bp[p * 32];
                float Ia = s.x * inv_b;
                float Da = cD * ((bN - s.x) - s.y);
                float Ib = s.z * inv_b;
                float Db = cD * ((bN - s.z) - s.w);
                if (k == 1 && p == 0) { Ia = 1.0f; Da = 0.0f; }  // exact t=0
                o4[p] = make_float4(Ia, Da, Ib, Db);
            }
        }
        __syncthreads();
    }
#undef SUBSTEP
}

extern "C" void kernel_launch(void* const* d_in, const int* in_sizes, int n_in,
                              void* d_out, int out_size) {
    const float* alpha = (const float*)d_in[0];
    float2* out = (float2*)d_out;
    sird_kernel<<<T_PTS / 32, 64>>>(alpha, out);
}

// round 15
// speedup vs baseline: 12.0962x; 1.3696x over previous
#include <cuda_runtime.h>

// SIRD batched integrator, sm_103a — round 14: RK4 @ dt=2 + quintic-Hermite
// dense output for odd time points, warp-specialized.
// 64 blocks x 96 threads: warp 0 integrates (1 scenario/lane, 1024 RK4 steps
// of dt=2), warps 1-2 reconstruct odd points and write output.
//
// Producer substep (2 time points): 23 FMA ops = 14 imm-form(rt1) + 9 reg(rt2)
// = 32 weighted issue cycles, 32-cycle chain -> ~16 cyc per output point.
//
// Odd point t=2j+1 from interval [2j, 2j+2] via two-point quintic Hermite
// (values + 1st + 2nd derivs at endpoints, tau = h/2 = 1):
//   m = (v0+v1)/2 + (5/16)(d0-d1) + (1/16)(s0+s1)
// Derivs in scaled vars (x,y)=(b*I,b*S):  x'=xy-gx, y'=-xy,
//   x''=x'(y-g) - x^2 y,  y''=-x'y + x^2 y.
// D reconstructed from the RK-preserved linear invariant: D=(mu/g)(N-S-I).

#define T_PTS  2048
#define NSTEP  1024                 // RK4 steps (dt=2) -> t=2..2048
#define BS     32                   // steps per batch
#define NB     (NSTEP / BS)         // 32 batches

__global__ void __launch_bounds__(96, 1)
sird_kernel(const float* __restrict__ alpha, float2* __restrict__ out) {
    __shared__ float4 buf[2][BS][32];   // [slot][step][lane] = (x0,y0,x1,y1)

    const int lane = threadIdx.x & 31;
    const int wid  = threadIdx.x >> 5;
    const int scen = blockIdx.x * 32 + lane;

    const float beta  = alpha[scen * 3 + 0];
    const float gamma = alpha[scen * 3 + 1];
    const float mu    = alpha[scen * 3 + 2];

    float b = fmaxf(beta * 1.0e-7f, 1.0e-20f);   // beta/N (scale-invariant guard)
    const float g = gamma + mu;

    // ---- producer constants (dt = 2) ----
    const float mg   = -g;
    const float m2g  = -2.0f * g;
    const float cA2  = 1.0f - g;
    constexpr float h6 = 1.0f / 3.0f;            // dt/6
    const float mh6g = h6 * mg;                  // -g/3
    float x = b;                                 // b * I0
    float y = b * (1.0e7f - 1.0f);               // b * S0

    // ---- consumer constants ----
    const float inv_b = 1.0f / b;
    const float cD    = (mu / fmaxf(g, 1.0e-30f)) * inv_b;
    const float bN    = b * 1.0e7f;
    float4* __restrict__ o4 =
        reinterpret_cast<float4*>(out + (size_t)scen * T_PTS);

#define SUBSTEP2() do {                                           \
        float f1   = y * x;                                       \
        float cAx  = cA2 * x;                                     \
        float x2   = fmaf( 1.0f, f1, cAx);                        \
        float y2   = fmaf(-1.0f, f1, y);                          \
        float f2   = y2 * x2;                                     \
        float in3  = fmaf(mg, x2, x);                             \
        float pxw  = fmaf(2.0f, x2, x);                           \
        float x3   = fmaf( 1.0f, f2, in3);                        \
        float y3   = fmaf(-1.0f, f2, y);                          \
        float pf   = fmaf(2.0f, f2, f1);                          \
        float f3   = y3 * x3;                                     \
        float in4  = fmaf(m2g, x3, x);                            \
        float pxw2 = fmaf(2.0f, x3, pxw);                         \
        float x4   = fmaf( 2.0f, f3, in4);                        \
        float y4   = fmaf(-2.0f, f3, y);                          \
        float pf3  = fmaf(2.0f, f3, pf);                          \
        float W    = fmaf(mh6g, pxw2, x);                         \
        float base = fmaf(h6, pf3, W);                            \
        float C    = fmaf(-h6, pf3, y);                           \
        float v    = fmaf(h6, y4, mh6g);                          \
        float f4   = y4 * x4;                                     \
        x = fmaf(x4, v, base);                                    \
        y = fmaf(-h6, f4, C);                                     \
    } while (0)

    for (int k = 0; k <= NB; ++k) {
        if (wid == 0) {
            if (k < NB) {
                float4* bp = &buf[k & 1][0][lane];
                #pragma unroll
                for (int i = 0; i < BS; ++i) {
                    float x0 = x, y0 = y;
                    SUBSTEP2();
                    bp[i * 32] = make_float4(x0, y0, x, y);
                }
            }
        } else if (k > 0) {
            const int kb   = k - 1;
            const int slot = kb & 1;
            const int half = (wid - 1) * (BS / 2);     // 0 or 16
            const float4* bp = &buf[slot][half][lane];
            float4* dst = o4 + kb * BS + half;
            #pragma unroll
            for (int ii = 0; ii < BS / 2; ++ii) {
                float4 s = bp[ii * 32];
                float x0 = s.x, y0 = s.y, x1 = s.z, y1 = s.w;
                // first/second derivatives at both endpoints
                float f0  = x0 * y0;
                float f1v = x1 * y1;
                float xp0 = fmaf(mg, x0, f0);
                float xp1 = fmaf(mg, x1, f1v);
                float t0  = y0 - g;
                float t1  = y1 - g;
                float xf0 = x0 * f0;
                float xf1 = x1 * f1v;
                float xpp0 = fmaf(xp0, t0, -xf0);
                float xpp1 = fmaf(xp1, t1, -xf1);
                float ypp0 = fmaf(-xp0, y0, xf0);
                float ypp1 = fmaf(-xp1, y1, xf1);
                // quintic Hermite midpoint (tau = 1)
                float mx = fmaf(0.0625f, xpp0 + xpp1,
                            fmaf(0.3125f, xp0 - xp1, 0.5f * (x0 + x1)));
                float my = fmaf(0.0625f, ypp0 + ypp1,
                            fmaf(0.3125f, f1v - f0, 0.5f * (y0 + y1)));
                // outputs: even point = left endpoint, odd = midpoint
                float Ie = x0 * inv_b;
                float De = cD * ((bN - x0) - y0);
                float Io = mx * inv_b;
                float Do = cD * ((bN - mx) - my);
                if (kb == 0 && half == 0 && ii == 0) { Ie = 1.0f; De = 0.0f; }
                dst[ii] = make_float4(Ie, De, Io, Do);
            }
        }
        __syncthreads();
    }
#undef SUBSTEP2
}

extern "C" void kernel_launch(void* const* d_in, const int* in_sizes, int n_in,
                              void* d_out, int out_size) {
    const float* alpha = (const float*)d_in[0];
    float2* out = (float2*)d_out;
    sird_kernel<<<T_PTS / 32, 96>>>(alpha, out);
}